// round 17
// baseline (speedup 1.0000x reference)
#include <cuda_runtime.h>
#include <cuda_fp16.h>
#include <math.h>
#include <stdint.h>

#define TT 4096
#define BB 4
#define DD 1024
#define NTOK (TT*BB)
#define CTOK 512
#define NCHUNK 32

// -------- scratch (fp16 intermediates) --------
__device__ __align__(128) __half g_xh[(size_t)NTOK*DD];
__device__ __align__(128) __half g_Wh[(size_t)3*DD*DD];
__device__ __align__(128) __half g_Q [(size_t)NTOK*DD];
__device__ __align__(128) __half g_K [(size_t)NTOK*DD];
__device__ __align__(128) __half g_Kt[(size_t)DD*NTOK];
__device__ __align__(128) __half g_Vt[(size_t)DD*NTOK];
__device__ __align__(128) __half g_S [(size_t)NCHUNK*DD*DD];
__device__ __align__(128) __half g_P [(size_t)NCHUNK*CTOK*CTOK];
__device__ float g_Zc[(size_t)NCHUNK*BB*DD];
__device__ float g_Dn[NTOK];

#define RSB   80                 // smem row stride bytes (32 halves + pad)
#define ATILE 10240              // 128 rows * 80B
#define BTILE 20480              // 256 rows * 80B
#define STAGE (ATILE + BTILE)    // 30720
#define NSTG  4
#define SMEMSZ (NSTG*STAGE)      // 122880
#define TRS   136                // transpose staging row stride (halves); 272B, 16B-aligned

__device__ __forceinline__ uint32_t smem_u32(const void* p){
    uint32_t a; asm("{ .reg .u64 t; cvta.to.shared.u64 t, %1; cvt.u32.u64 %0, t; }":"=r"(a):"l"(p)); return a;
}
__device__ __forceinline__ void cp16(uint32_t s, const void* g){
    asm volatile("cp.async.cg.shared.global [%0], [%1], 16;" :: "r"(s), "l"(g));
}

// shared staging helper macros (identical math to R8 core)
#define STAGE_DECL                                                            \
    const int a0 = tid*2, a1 = tid*2 + 1;                                     \
    const int b0 = tid*4;                                                     \
    const uint32_t acs0 = sbase + (a0>>2)*RSB + (a0&3)*16;                    \
    const uint32_t acs1 = sbase + (a1>>2)*RSB + (a1&3)*16;                    \
    const uint32_t bcs0 = sbase + ATILE + ((b0  )>>2)*RSB + ((b0  )&3)*16;    \
    const uint32_t bcs1 = sbase + ATILE + ((b0+1)>>2)*RSB + ((b0+1)&3)*16;    \
    const uint32_t bcs2 = sbase + ATILE + ((b0+2)>>2)*RSB + ((b0+2)&3)*16;    \
    const uint32_t bcs3 = sbase + ATILE + ((b0+3)>>2)*RSB + ((b0+3)&3)*16;    \
    const __half *acp0, *acp1, *bcp0, *bcp1, *bcp2, *bcp3;

#define STAGE_SETUP(Abase, lda_, Bbase, ldb_)                                 \
    acp0 = (Abase) + (long)(row0 + (a0>>2))*(lda_) + (a0&3)*8;                \
    acp1 = (Abase) + (long)(row0 + (a1>>2))*(lda_) + (a1&3)*8;                \
    bcp0 = (Bbase) + (long)(col0 + ((b0  )>>2))*(ldb_) + ((b0  )&3)*8;        \
    bcp1 = (Bbase) + (long)(col0 + ((b0+1)>>2))*(ldb_) + ((b0+1)&3)*8;       \
    bcp2 = (Bbase) + (long)(col0 + ((b0+2)>>2))*(ldb_) + ((b0+2)&3)*8;       \
    bcp3 = (Bbase) + (long)(col0 + ((b0+3)>>2))*(ldb_) + ((b0+3)&3)*8;

#define FRAG_DECL                                                             \
    const uint32_t a_lm = (uint32_t)(wm*64*RSB + (lane&15)*RSB + (lane>>4)*16); \
    const uint32_t b_lm = (uint32_t)(ATILE + wn*64*RSB                        \
                        + ((lane&7) + ((lane>>4)&1)*8)*RSB + ((lane>>3)&1)*16);

#define DEF_LOADCP                                                            \
    auto loadcp = [&](int st, int k0){                                        \
        uint32_t so = st*STAGE;                                               \
        cp16(acs0 + so, acp0 + k0);                                           \
        cp16(acs1 + so, acp1 + k0);                                           \
        cp16(bcs0 + so, bcp0 + k0);                                           \
        cp16(bcs1 + so, bcp1 + k0);                                           \
        cp16(bcs2 + so, bcp2 + k0);                                           \
        cp16(bcs3 + so, bcp3 + k0);                                           \
        asm volatile("cp.async.commit_group;" ::: "memory");                  \
    };

#define DEF_MMASTAGE                                                          \
    auto mma_stage = [&](int st){                                             \
        uint32_t base = sbase + st*STAGE;                                     \
        _Pragma("unroll")                                                     \
        for (int kk = 0; kk < 2; kk++){                                       \
            uint32_t af[4][4], bf[8][2];                                      \
            _Pragma("unroll")                                                 \
            for (int mt = 0; mt < 4; mt++){                                   \
                uint32_t ad = base + a_lm + mt*(16*RSB) + kk*32;              \
                asm volatile("ldmatrix.sync.aligned.m8n8.x4.shared.b16 {%0,%1,%2,%3},[%4];" \
                    : "=r"(af[mt][0]),"=r"(af[mt][1]),"=r"(af[mt][2]),"=r"(af[mt][3]) \
                    : "r"(ad));                                               \
            }                                                                 \
            _Pragma("unroll")                                                 \
            for (int p = 0; p < 4; p++){                                      \
                uint32_t bd = base + b_lm + p*(16*RSB) + kk*32;               \
                uint32_t r0,r1,r2,r3;                                         \
                asm volatile("ldmatrix.sync.aligned.m8n8.x4.shared.b16 {%0,%1,%2,%3},[%4];" \
                    : "=r"(r0),"=r"(r1),"=r"(r2),"=r"(r3) : "r"(bd));         \
                bf[2*p][0]=r0; bf[2*p][1]=r1; bf[2*p+1][0]=r2; bf[2*p+1][1]=r3; \
            }                                                                 \
            _Pragma("unroll")                                                 \
            for (int mt = 0; mt < 4; mt++)                                    \
                _Pragma("unroll")                                             \
                for (int nt = 0; nt < 8; nt++)                                \
                    asm volatile(                                             \
                        "mma.sync.aligned.m16n8k16.row.col.f32.f16.f16.f32 "  \
                        "{%0,%1,%2,%3},{%4,%5,%6,%7},{%8,%9},{%0,%1,%2,%3};"  \
                        : "+f"(acc[mt][nt][0]),"+f"(acc[mt][nt][1]),          \
                          "+f"(acc[mt][nt][2]),"+f"(acc[mt][nt][3])           \
                        : "r"(af[mt][0]),"r"(af[mt][1]),"r"(af[mt][2]),"r"(af[mt][3]), \
                          "r"(bf[nt][0]),"r"(bf[nt][1]));                     \
        }                                                                     \
    };

#define DEF_PIPELINE                                                          \
    auto run_pipeline = [&](int n){                                           \
        loadcp(0, 0);                                                         \
        loadcp(1, 32);                                                        \
        loadcp(2, 64);                                                        \
        for (int s = 0; s < n; s++){                                          \
            if (s < n-2)       asm volatile("cp.async.wait_group 2;" ::: "memory"); \
            else if (s == n-2) asm volatile("cp.async.wait_group 1;" ::: "memory"); \
            else               asm volatile("cp.async.wait_group 0;" ::: "memory"); \
            __syncthreads();                                                  \
            if (s + 3 < n) loadcp((s+3)&3, (s+3)*32);                         \
            mma_stage(s & 3);                                                 \
        }                                                                     \
    };

// =====================================================================
// dual GEMM: one launch for step 4 (S = Vt·Kt^T) and step 8 (P = mask(Q·K^T))
// =====================================================================
__global__ void __launch_bounds__(256, 1) dual_gemm(
    const __half* __restrict__ Vth, const __half* __restrict__ Kth,
    __half* __restrict__ Sh,
    const __half* __restrict__ Qh, const __half* __restrict__ Kh,
    __half* __restrict__ Ph)
{
    extern __shared__ char smem[];
    const uint32_t sbase = smem_u32(smem);
    const int tid  = threadIdx.x;
    const int lane = tid & 31;
    const int warp = tid >> 5;
    const int wm = warp >> 2, wn = warp & 3;
    const int gid = lane >> 2, tig = lane & 3;
    const int chunk = blockIdx.y;
    const int xid = blockIdx.x;
    const bool isP = (xid >= 32);

    const __half *Ah, *Bh; __half* Chh;
    int lda, ldb, ldc, Kdim, row0, col0;
    if (!isP){
        int xx = xid & 3, yy = xid >> 2;
        Ah = Vth + (long)chunk*CTOK;  lda = NTOK;
        Bh = Kth + (long)chunk*CTOK;  ldb = NTOK;
        Chh = Sh + (size_t)chunk*DD*DD; ldc = DD;
        Kdim = CTOK; row0 = yy*128; col0 = xx*256;
    } else {
        int t = xid - 32;
        int xx = t & 1, yy = t >> 1;
        Ah = Qh + (long)chunk*CTOK*DD; lda = DD;
        Bh = Kh + (long)chunk*CTOK*DD; ldb = DD;
        Chh = Ph + (size_t)chunk*CTOK*CTOK; ldc = CTOK;
        Kdim = DD; row0 = yy*128; col0 = xx*256;
    }

    if (isP && ((col0 >> 2) > ((row0 + 127) >> 2))){
        #pragma unroll
        for (int it = 0; it < 16; it++){
            int task = it*256 + tid;
            int r = task >> 5, ch = task & 31;
            uint4 z = make_uint4(0,0,0,0);
            *(uint4*)&Chh[(long)(row0 + r)*ldc + col0 + ch*8] = z;
        }
        return;
    }

    float acc[4][8][4] = {};
    FRAG_DECL
    STAGE_DECL
    STAGE_SETUP(Ah, lda, Bh, ldb)
    DEF_LOADCP
    DEF_MMASTAGE
    DEF_PIPELINE

    run_pipeline(Kdim >> 5);

    #pragma unroll
    for (int mt = 0; mt < 4; mt++){
        int r0 = row0 + wm*64 + mt*16 + gid;
        int r1 = r0 + 8;
        #pragma unroll
        for (int nt = 0; nt < 8; nt++){
            int c0 = col0 + wn*64 + nt*8 + 2*tig;
            float v[4];
            #pragma unroll
            for (int e = 0; e < 4; e++){
                float f = acc[mt][nt][e];
                if (isP){
                    int r = (e < 2) ? r0 : r1;
                    int c = c0 + (e & 1);
                    if ((c >> 2) > (r >> 2)) f = 0.0f;
                }
                v[e] = f;
            }
            *(__half2*)(Chh + (long)r0*ldc + c0) = __floats2half2_rn(v[0], v[1]);
            *(__half2*)(Chh + (long)r1*ldc + c0) = __floats2half2_rn(v[2], v[3]);
        }
    }
}

// =====================================================================
// fused Q/K/V projection: grid (12,128)
// Q: elu1 -> Qh ; K: elu1 -> Kh + Kt (smem-staged coalesced) ; V: Vt only
// =====================================================================
__global__ void __launch_bounds__(256, 1) proj_kernel(
    const __half* __restrict__ xh, const __half* __restrict__ Wall,
    __half* __restrict__ Qh, __half* __restrict__ Kh,
    __half* __restrict__ Kth, __half* __restrict__ Vth)
{
    extern __shared__ char smem[];
    const uint32_t sbase = smem_u32(smem);
    const int tid  = threadIdx.x;
    const int lane = tid & 31;
    const int warp = tid >> 5;
    const int wm = warp >> 2, wn = warp & 3;
    const int gid = lane >> 2, tig = lane & 3;
    const int m    = blockIdx.x >> 2;            // 0=Q 1=K 2=V
    const int col0 = (blockIdx.x & 3) * 256;
    const int row0 = blockIdx.y * 128;

    const __half* Ah = xh;
    const __half* Bh = Wall + (size_t)m*DD*DD;

    float acc[4][8][4] = {};
    FRAG_DECL
    STAGE_DECL
    STAGE_SETUP(Ah, DD, Bh, DD)
    DEF_LOADCP
    DEF_MMASTAGE
    DEF_PIPELINE

    run_pipeline(DD >> 5);

    const bool act = (m < 2);
    __half* Cn = (m == 0) ? Qh : Kh;
    __half* Ct = (m == 1) ? Kth : Vth;

    // first pass: activation + row-major store (Q,K); keep post-act in acc
    #pragma unroll
    for (int mt = 0; mt < 4; mt++){
        int r0 = row0 + wm*64 + mt*16 + gid;
        int r1 = r0 + 8;
        #pragma unroll
        for (int nt = 0; nt < 8; nt++){
            int c0 = col0 + wn*64 + nt*8 + 2*tig;
            float v[4];
            #pragma unroll
            for (int e = 0; e < 4; e++){
                float f = acc[mt][nt][e];
                if (act) f = (f > 0.0f) ? (f + 1.0f) : expf(f);
                v[e] = f;
                acc[mt][nt][e] = f;
            }
            if (m <= 1){
                *(__half2*)(Cn + (long)r0*DD + c0) = __floats2half2_rn(v[0], v[1]);
                *(__half2*)(Cn + (long)r1*DD + c0) = __floats2half2_rn(v[2], v[3]);
            }
        }
    }

    // second pass (K,V only): smem-staged transpose, coalesced 16B stores
    if (m >= 1){
        __syncthreads();                         // pipeline smem now reusable
        __half* buf = (__half*)smem;             // [256 cols][TRS] halves
        #pragma unroll
        for (int mt = 0; mt < 4; mt++){
            int rl0 = wm*64 + mt*16 + gid;       // local row 0..127
            int rl1 = rl0 + 8;
            #pragma unroll
            for (int nt = 0; nt < 8; nt++){
                int cl = wn*64 + nt*8 + 2*tig;   // local col 0..255
                buf[(size_t)cl     *TRS + rl0] = __float2half(acc[mt][nt][0]);
                buf[(size_t)(cl+1) *TRS + rl0] = __float2half(acc[mt][nt][1]);
                buf[(size_t)cl     *TRS + rl1] = __float2half(acc[mt][nt][2]);
                buf[(size_t)(cl+1) *TRS + rl1] = __float2half(acc[mt][nt][3]);
            }
        }
        __syncthreads();
        // 256 cols x 16 chunks of 8 halves = 4096 tasks / 256 threads = 16 iters
        #pragma unroll
        for (int it = 0; it < 16; it++){
            int task = it*256 + tid;
            int c = task >> 4, j = task & 15;
            uint4 val = *(uint4*)&buf[(size_t)c*TRS + j*8];
            *(uint4*)&Ct[(long)(col0 + c)*NTOK + row0 + j*8] = val;
        }
    }
}

// =====================================================================
// fused steps 7+9: Y = (Q_c·Sprefix_c^T + P_c·Vt_c^T) / denom  (fp32 out)
// =====================================================================
__global__ void __launch_bounds__(256, 1) fused79_kernel(
    const __half* __restrict__ Qh, const __half* __restrict__ Sh,
    const __half* __restrict__ Ph, const __half* __restrict__ Vth,
    const float* __restrict__ Dn, float* __restrict__ out)
{
    extern __shared__ char smem[];
    const uint32_t sbase = smem_u32(smem);
    const int tid  = threadIdx.x;
    const int lane = tid & 31;
    const int warp = tid >> 5;
    const int wm = warp >> 2, wn = warp & 3;
    const int gid = lane >> 2, tig = lane & 3;
    const int bz = blockIdx.z;
    const int row0 = blockIdx.y * 128;
    const int col0 = blockIdx.x * 256;

    float acc[4][8][4] = {};
    FRAG_DECL
    STAGE_DECL
    DEF_LOADCP
    DEF_MMASTAGE
    DEF_PIPELINE

    STAGE_SETUP(Qh + (long)bz*CTOK*DD, DD, Sh + (size_t)bz*DD*DD, DD)
    run_pipeline(DD >> 5);

    STAGE_SETUP(Ph + (size_t)bz*CTOK*CTOK, CTOK, Vth + (long)bz*CTOK, NTOK)
    run_pipeline(CTOK >> 5);

    float* Cf = out + (long)bz*CTOK*DD;
    #pragma unroll
    for (int mt = 0; mt < 4; mt++){
        int r0 = row0 + wm*64 + mt*16 + gid;
        int r1 = r0 + 8;
        float dn0 = Dn[(long)bz*CTOK + r0];
        float dn1 = Dn[(long)bz*CTOK + r1];
        #pragma unroll
        for (int nt = 0; nt < 8; nt++){
            int c0 = col0 + wn*64 + nt*8 + 2*tig;
            float2 p0 = make_float2(acc[mt][nt][0]/dn0, acc[mt][nt][1]/dn0);
            float2 p1 = make_float2(acc[mt][nt][2]/dn1, acc[mt][nt][3]/dn1);
            *(float2*)(Cf + (long)r0*DD + c0) = p0;
            *(float2*)(Cf + (long)r1*DD + c0) = p1;
        }
    }
}

// -------- single-launch fp32 -> fp16 conversion (x | Wq | Wk | Wv) --------
#define N8X (NTOK*DD/8)
#define N8W (DD*DD/8)
__global__ void f2h_all_kernel(const float* __restrict__ x,
                               const float* __restrict__ Wq,
                               const float* __restrict__ Wk,
                               const float* __restrict__ Wv,
                               __half* __restrict__ xh, __half* __restrict__ Wh)
{
    int i = blockIdx.x * blockDim.x + threadIdx.x;
    const float* src; __half* dst; int l;
    if (i < N8X)            { src = x;  dst = xh;            l = i; }
    else if (i < N8X+N8W)   { src = Wq; dst = Wh;            l = i - N8X; }
    else if (i < N8X+2*N8W) { src = Wk; dst = Wh + (size_t)DD*DD;   l = i - N8X - N8W; }
    else if (i < N8X+3*N8W) { src = Wv; dst = Wh + (size_t)2*DD*DD; l = i - N8X - 2*N8W; }
    else return;
    float4 a = ((const float4*)src)[2*l];
    float4 b = ((const float4*)src)[2*l+1];
    __half2 h[4] = { __floats2half2_rn(a.x,a.y), __floats2half2_rn(a.z,a.w),
                     __floats2half2_rn(b.x,b.y), __floats2half2_rn(b.z,b.w) };
    ((uint4*)dst)[l] = *(uint4*)h;
}

// -------- merged aux: prefix of S (blocks 0..1023) + K chunk sums (1024..1535) --------
__global__ void __launch_bounds__(256) aux_kernel(
    __half* __restrict__ S, const __half* __restrict__ Kp, float* __restrict__ Zc)
{
    if (blockIdx.x < 1024){
        // exclusive prefix over chunks: uint2/thread, ring prefetch (proven R16)
        size_t base = ((size_t)blockIdx.x * blockDim.x + threadIdx.x) * 4;
        float acc[4] = {0,0,0,0};
        uint2 ring[2];
        ring[0] = *(const uint2*)&S[base];
        ring[1] = *(const uint2*)&S[(size_t)DD*DD + base];
        #pragma unroll 4
        for (int c = 0; c < NCHUNK; c++){
            size_t off = (size_t)c*DD*DD + base;
            uint2 cur = ring[c & 1];
            if (c + 2 < NCHUNK)
                ring[c & 1] = *(const uint2*)&S[off + (size_t)2*DD*DD];
            __half2* hp = (__half2*)&cur;
            uint2 outv; __half2* op = (__half2*)&outv;
            #pragma unroll
            for (int i = 0; i < 2; i++){
                float2 f = __half22float2(hp[i]);
                op[i] = __floats2half2_rn(acc[2*i], acc[2*i+1]);
                acc[2*i]   += f.x;
                acc[2*i+1] += f.y;
            }
            *(uint2*)&S[off] = outv;
        }
    } else {
        int id = (blockIdx.x - 1024) * blockDim.x + threadIdx.x;   // < NCHUNK*4096
        int c = id >> 12, bd = id & 4095;
        const __half* p = Kp + (long)c*128*4096 + bd;
        float s = 0.0f;
        #pragma unroll 8
        for (int t = 0; t < 128; t++) s += __half2float(p[(long)t*4096]);
        Zc[id] = s;
    }
}

// -------- fused cumsum+dot with prefetch: Dn[token] = Q[token] . zcum[token] --------
__global__ void __launch_bounds__(1024) zdot_kernel(
    const __half* __restrict__ Kp, const __half* __restrict__ Qp,
    const float* __restrict__ Zc, float* __restrict__ Dn)
{
    __shared__ float part[128][33];
    const int c = blockIdx.x >> 2;
    const int b = blockIdx.x & 3;
    const int d = threadIdx.x;
    const int lane = d & 31, w = d >> 5;

    float acc = 0.0f;
    for (int cp = 0; cp < c; cp++) acc += Zc[cp*4096 + b*1024 + d];

    const long base = ((long)(c*128)*4 + b)*1024 + d;
    __half kcur = Kp[base];
    __half qcur = Qp[base];
    #pragma unroll 4
    for (int t = 0; t < 128; t++){
        __half knxt, qnxt;
        if (t + 1 < 128){
            long offn = base + (long)(t+1)*4096;
            knxt = Kp[offn];
            qnxt = Qp[offn];
        }
        acc += __half2float(kcur);
        float s = __half2float(qcur) * acc;
        #pragma unroll
        for (int o = 16; o; o >>= 1) s += __shfl_down_sync(0xffffffffu, s, o);
        if (lane == 0) part[t][w] = s;
        kcur = knxt; qcur = qnxt;
    }
    __syncthreads();
    if (d < 128){
        float s = 0.0f;
        #pragma unroll
        for (int i = 0; i < 32; i++) s += part[d][i];
        Dn[((long)(c*128 + d))*4 + b] = s;
    }
}

extern "C" void kernel_launch(void* const* d_in, const int* in_sizes, int n_in,
                              void* d_out, int out_size)
{
    const float* x  = (const float*)d_in[0];
    const float* Wq = (const float*)d_in[1];
    const float* Wk = (const float*)d_in[2];
    const float* Wv = (const float*)d_in[3];
    float* out = (float*)d_out;

    __half *xh,*Wh,*Qh,*Kh,*Kth,*Vth,*Sh,*Ph; float *Zc,*Dn;
    cudaGetSymbolAddress((void**)&xh,  g_xh);
    cudaGetSymbolAddress((void**)&Wh,  g_Wh);
    cudaGetSymbolAddress((void**)&Qh,  g_Q);
    cudaGetSymbolAddress((void**)&Kh,  g_K);
    cudaGetSymbolAddress((void**)&Kth, g_Kt);
    cudaGetSymbolAddress((void**)&Vth, g_Vt);
    cudaGetSymbolAddress((void**)&Sh,  g_S);
    cudaGetSymbolAddress((void**)&Ph,  g_P);
    cudaGetSymbolAddress((void**)&Zc,  g_Zc);
    cudaGetSymbolAddress((void**)&Dn,  g_Dn);

    cudaFuncSetAttribute(proj_kernel,    cudaFuncAttributeMaxDynamicSharedMemorySize, SMEMSZ);
    cudaFuncSetAttribute(dual_gemm,      cudaFuncAttributeMaxDynamicSharedMemorySize, SMEMSZ);
    cudaFuncSetAttribute(fused79_kernel, cudaFuncAttributeMaxDynamicSharedMemorySize, SMEMSZ);

    // 0) convert all inputs to fp16, one launch
    f2h_all_kernel<<<(N8X + 3*N8W + 255)/256, 256>>>(x, Wq, Wk, Wv, xh, Wh);

    // 1) fused projections: Q, K (+Kt staged), Vt (staged)
    proj_kernel<<<dim3(12,128,1),256,SMEMSZ>>>(xh, Wh, Qh, Kh, Kth, Vth);

    // 2) S chunks + masked P, one launch
    dual_gemm<<<dim3(40,NCHUNK,1),256,SMEMSZ>>>(Vth, Kth, Sh, Qh, Kh, Ph);

    // 3) merged: S prefix + K chunk sums
    aux_kernel<<<1536, 256>>>(Sh, Kh, Zc);

    // 4) fused cumsum-dot denominator
    zdot_kernel<<<NCHUNK*BB, 1024>>>(Kh, Qh, Zc, Dn);

    // 5) Y = (Q_c·Sprefix^T + P_c·Vt^T) / denom
    fused79_kernel<<<dim3(4,4,NCHUNK),256,SMEMSZ>>>(Qh, Sh, Ph, Vth, Dn, out);
}